// round 7
// baseline (speedup 1.0000x reference)
#include <cuda_runtime.h>
#include <cuda_bf16.h>
#include <math.h>

#define NB 8
#define LL 4096
#define HH 8
#define DD 64
#define HT 64
#define WD 64
#define NHH (NB*HH)          // 64
#define CHUNKS 8
#define CROWS (LL/CHUNKS)    // 512
#define ROWSTRIDE (HH*DD)    // 512
#define TILE_L 128

typedef unsigned long long ull;

// ---------------- device scratch ----------------
__device__ float g_kvp[CHUNKS][NHH][DD][DD];
__device__ float g_ksp[CHUNKS][NHH][DD];
__device__ float g_kv[NHH][DD][DD];
__device__ float g_ksum[NHH][DD];

// ---------------- f32x2 helpers ----------------
__device__ __forceinline__ void ffma2(ull& d, ull a, ull b){
    asm("fma.rn.f32x2 %0, %1, %2, %0;" : "+l"(d) : "l"(a), "l"(b));
}
__device__ __forceinline__ ull pack2(float lo, float hi){
    ull r; asm("mov.b64 %0, {%1, %2};" : "=l"(r) : "f"(lo), "f"(hi)); return r;
}
__device__ __forceinline__ void f4add(float4& a, const float4 b){
    a.x += b.x; a.y += b.y; a.z += b.z; a.w += b.w;
}
__device__ __forceinline__ float softinv(float p){
    float s = (p > 20.f) ? p : log1pf(expf(p));
    return 1.f / s;
}

// ---------------- K1: kv & ksum partials (R2-proven shape, CHUNKS=8) ----------------
__global__ void __launch_bounds__(64) k_kv(const float* __restrict__ keys,
                                           const float* __restrict__ values,
                                           const float* __restrict__ sp){
    __shared__ float4 kt4[64*16];
    __shared__ float4 vt4[64*16];
    __shared__ float invs[64];

    const int nh    = blockIdx.x & (NHH-1);
    const int chunk = blockIdx.x >> 6;
    const int n = nh >> 3, h = nh & 7;
    const int t = threadIdx.x;
    const int td = t >> 3, tj = t & 7;
    invs[t] = softinv(sp[t]);
    __syncthreads();

    const size_t base = ((size_t)(n*LL + chunk*CROWS)*HH + h)*DD;

    ull acc[8][4];
    #pragma unroll
    for (int a = 0; a < 8; ++a)
        #pragma unroll
        for (int b = 0; b < 4; ++b) acc[a][b] = 0ull;
    float4 ksA = make_float4(0,0,0,0), ksB = make_float4(0,0,0,0);

    for (int stage = 0; stage < CROWS/64; ++stage){
        __syncthreads();
        const int r = stage*64 + t;
        const float4* kp = (const float4*)(keys   + base + (size_t)r*ROWSTRIDE);
        const float4* vp = (const float4*)(values + base + (size_t)r*ROWSTRIDE);
        float4 c[16];
        float s2 = 0.f, s6 = 0.f;
        #pragma unroll
        for (int i = 0; i < 16; ++i){
            float4 k4 = kp[i], iv = ((const float4*)invs)[i], x, cc;
            x.x = (fmaxf(k4.x,0.f)+1e-6f)*iv.x;
            x.y = (fmaxf(k4.y,0.f)+1e-6f)*iv.y;
            x.z = (fmaxf(k4.z,0.f)+1e-6f)*iv.z;
            x.w = (fmaxf(k4.w,0.f)+1e-6f)*iv.w;
            cc.x = x.x*x.x*x.x; cc.y = x.y*x.y*x.y;
            cc.z = x.z*x.z*x.z; cc.w = x.w*x.w*x.w;
            s2 += x.x*x.x + x.y*x.y + x.z*x.z + x.w*x.w;
            s6 += cc.x*cc.x + cc.y*cc.y + cc.z*cc.z + cc.w*cc.w;
            c[i] = cc;
        }
        const float rt = sqrtf(s2/s6);
        const int swb = t & 15;
        #pragma unroll
        for (int i = 0; i < 16; ++i){
            float4 cc = c[i];
            cc.x *= rt; cc.y *= rt; cc.z *= rt; cc.w *= rt;
            kt4[t*16 + (i ^ swb)] = cc;
            vt4[t*16 + (i ^ swb)] = vp[i];
        }
        __syncthreads();

        #pragma unroll 4
        for (int r2 = 0; r2 < 64; ++r2){
            const int sw = r2 & 15;
            const float4 a0 = kt4[r2*16 + ((td*2  ) ^ sw)];
            const float4 a1 = kt4[r2*16 + ((td*2+1) ^ sw)];
            const ulonglong2 b0 = *(const ulonglong2*)&vt4[r2*16 + ((tj*2  ) ^ sw)];
            const ulonglong2 b1 = *(const ulonglong2*)&vt4[r2*16 + ((tj*2+1) ^ sw)];
            if (tj == 0){ f4add(ksA, a0); f4add(ksB, a1); }
            const float ka[8] = {a0.x,a0.y,a0.z,a0.w,a1.x,a1.y,a1.z,a1.w};
            #pragma unroll
            for (int dd = 0; dd < 8; ++dd){
                const ull k2 = pack2(ka[dd], ka[dd]);
                ffma2(acc[dd][0], k2, b0.x);
                ffma2(acc[dd][1], k2, b0.y);
                ffma2(acc[dd][2], k2, b1.x);
                ffma2(acc[dd][3], k2, b1.y);
            }
        }
    }

    #pragma unroll
    for (int dd = 0; dd < 8; ++dd){
        ull* o = (ull*)&g_kvp[chunk][nh][td*8+dd][tj*8];
        o[0]=acc[dd][0]; o[1]=acc[dd][1]; o[2]=acc[dd][2]; o[3]=acc[dd][3];
    }
    if (tj == 0){
        ((float4*)&g_ksp[chunk][nh][td*8])[0] = ksA;
        ((float4*)&g_ksp[chunk][nh][td*8])[1] = ksB;
    }
}

// ---------------- K1b: parallel deterministic chunk reduction ----------------
__global__ void __launch_bounds__(128) k_kvreduce(){
    const int gid = blockIdx.x*128 + threadIdx.x;   // 65536 float4 outputs
    const float4* src = (const float4*)g_kvp;
    float4 s = make_float4(0,0,0,0);
    #pragma unroll
    for (int c = 0; c < CHUNKS; ++c) f4add(s, src[(size_t)c*65536 + gid]);
    ((float4*)g_kv)[gid] = s;
    if (gid < NHH*DD){
        const float* ks = (const float*)g_ksp;
        float acc = 0.f;
        #pragma unroll
        for (int c = 0; c < CHUNKS; ++c) acc += ks[c*NHH*DD + gid];
        ((float*)g_ksum)[gid] = acc;
    }
}

// ---------------- K2: FUSED attention GEMM + depthwise conv + bias ----------------
// 256 threads, tile 128 L-rows (= 2 image rows). Thread = 8 rows x 4 d-cols,
// lanes = d-pairs. acc starts at bias, conv adds via direct v LDG (L1-cached
// window), transform fills qt, GEMM accumulates (m*a)*kv. Single STG epilogue.
#define SM_WSH2   0
#define SM_KV     (SM_WSH2 + 25*32*8)               // 6400
#define SM_QT     (SM_KV + 64*68*4)                 // +17408
#define SM_KSUM   (SM_QT + 64*132*4)                // +33792
#define SM_INV    (SM_KSUM + 256)
#define SM_M      (SM_INV + 256)
#define ATTN_SMEM (SM_M + 512)
__global__ void __launch_bounds__(256) k_attn(const float* __restrict__ qin,
                                              const float* __restrict__ vin,
                                              const float* __restrict__ wt,
                                              const float* __restrict__ bias,
                                              const float* __restrict__ sp,
                                              float* __restrict__ out){
    extern __shared__ char smraw[];
    ull*   wsh2   = (ull*)(smraw + SM_WSH2);     // [25 taps][32 d-pairs]
    float* kv_s   = (float*)(smraw + SM_KV);     // 64 x 68
    float* qt     = (float*)(smraw + SM_QT);     // 64 x 132
    float* ksum_s = (float*)(smraw + SM_KSUM);
    float* invs   = (float*)(smraw + SM_INV);
    float* m_s    = (float*)(smraw + SM_M);

    const int lt = blockIdx.x & 31;
    const int nh = blockIdx.x >> 5;
    const int n = nh >> 3, h = nh & 7;
    const int t = threadIdx.x;
    const int tr = t >> 4, tc = t & 15;

    {   // smem fills: kv (padded), weights (d-paired), ksum, inv scale
        const int d = t >> 2, qf = t & 3;
        const float4* src = (const float4*)&g_kv[nh][d][0];
        float4* dst = (float4*)&kv_s[d*68];
        #pragma unroll
        for (int i = 0; i < 4; ++i) dst[qf*4 + i] = src[qf*4 + i];
        #pragma unroll
        for (int i = t; i < 25*32; i += 256){
            const int tap = i >> 5, dp = i & 31;
            wsh2[i] = pack2(wt[(2*dp)*25 + tap], wt[(2*dp+1)*25 + tap]);
        }
        if (t < DD){ ksum_s[t] = g_ksum[nh][t]; invs[t] = softinv(sp[t]); }
    }

    // ---- conv phase: acc = bias + conv(v), lanes = d-pairs (tc*4 .. tc*4+3)
    ull acc[8][2];
    {
        const ulonglong2 bb = *(const ulonglong2*)(bias + tc*4);
        #pragma unroll
        for (int xx = 0; xx < 8; ++xx){ acc[xx][0] = bb.x; acc[xx][1] = bb.y; }

        const int y  = lt*2 + (tr >> 3);
        const int x0 = (tr & 7)*8;
        const float* vbase = vin + ((size_t)(n*LL)*HH + h)*DD + tc*4;
        // wait for wsh2 fill
        __syncthreads();

        #pragma unroll
        for (int dy = 0; dy < 5; ++dy){
            const int yy = y - 2 + dy;
            ulonglong2 win[12];
            if (yy >= 0 && yy < HT){
                #pragma unroll
                for (int i = 0; i < 12; ++i){
                    const int xx = x0 - 2 + i;
                    if (xx >= 0 && xx < WD)
                        win[i] = *(const ulonglong2*)(vbase + (size_t)(yy*WD + xx)*ROWSTRIDE);
                    else win[i] = make_ulonglong2(0ull, 0ull);
                }
            } else {
                #pragma unroll
                for (int i = 0; i < 12; ++i) win[i] = make_ulonglong2(0ull, 0ull);
            }
            const ull* wp = wsh2 + dy*5*32;
            #pragma unroll
            for (int dx = 0; dx < 5; ++dx){
                const ull w0 = wp[dx*32 + tc*2];
                const ull w1 = wp[dx*32 + tc*2 + 1];
                #pragma unroll
                for (int xx = 0; xx < 8; ++xx){
                    ffma2(acc[xx][0], w0, win[xx+dx].x);
                    ffma2(acc[xx][1], w1, win[xx+dx].y);
                }
            }
        }
    }

    const size_t base = ((size_t)(n*LL + lt*TILE_L)*HH + h)*DD;

    // ---- transform phase: row t (t<128), unscaled cc into qt, m saved
    if (t < TILE_L){
        const float4* qp = (const float4*)(qin + base + (size_t)t*ROWSTRIDE);
        float s2 = 0.f, s6 = 0.f, sd = 0.f;
        #pragma unroll
        for (int i = 0; i < 16; ++i){
            float4 q4 = qp[i];
            float4 iv = ((const float4*)invs)[i];
            float4 ks = ((const float4*)ksum_s)[i];
            float4 x, cc;
            x.x = (fmaxf(q4.x,0.f)+1e-6f)*iv.x;
            x.y = (fmaxf(q4.y,0.f)+1e-6f)*iv.y;
            x.z = (fmaxf(q4.z,0.f)+1e-6f)*iv.z;
            x.w = (fmaxf(q4.w,0.f)+1e-6f)*iv.w;
            cc.x = x.x*x.x*x.x; cc.y = x.y*x.y*x.y;
            cc.z = x.z*x.z*x.z; cc.w = x.w*x.w*x.w;
            s2 += x.x*x.x + x.y*x.y + x.z*x.z + x.w*x.w;
            s6 += cc.x*cc.x + cc.y*cc.y + cc.z*cc.z + cc.w*cc.w;
            sd += cc.x*ks.x + cc.y*ks.y + cc.z*ks.z + cc.w*ks.w;
            qt[(4*i+0)*132 + t] = cc.x;
            qt[(4*i+1)*132 + t] = cc.y;
            qt[(4*i+2)*132 + t] = cc.z;
            qt[(4*i+3)*132 + t] = cc.w;
        }
        const float rt = sqrtf(s2/s6);
        const float z  = 1.f / (rt*sd + 1e-6f);
        m_s[t] = rt * z;
    }
    __syncthreads();

    // ---- GEMM phase: acc += (m[row]*a[row][d]) * kv[d][col-pair]
    float mr[8];
    #pragma unroll
    for (int rr = 0; rr < 8; ++rr) mr[rr] = m_s[tr*8 + rr];

    #pragma unroll 4
    for (int d = 0; d < DD; ++d){
        const float4 a0 = *(const float4*)&qt[d*132 + tr*8];
        const float4 a1 = *(const float4*)&qt[d*132 + tr*8 + 4];
        const ulonglong2 b = *(const ulonglong2*)&kv_s[d*68 + tc*4];
        const float as[8] = {a0.x,a0.y,a0.z,a0.w,a1.x,a1.y,a1.z,a1.w};
        #pragma unroll
        for (int rr = 0; rr < 8; ++rr){
            const float am = as[rr]*mr[rr];
            const ull ad = pack2(am, am);
            ffma2(acc[rr][0], ad, b.x);
            ffma2(acc[rr][1], ad, b.y);
        }
    }

    // ---- epilogue: single write (no read)
    float* ob = out + base + (size_t)(tr*8)*ROWSTRIDE + tc*4;
    #pragma unroll
    for (int rr = 0; rr < 8; ++rr)
        *(ulonglong2*)(ob + (size_t)rr*ROWSTRIDE) = make_ulonglong2(acc[rr][0], acc[rr][1]);
}

// ---------------- launch: 3 kernels, single stream ----------------
extern "C" void kernel_launch(void* const* d_in, const int* in_sizes, int n_in,
                              void* d_out, int out_size){
    const float* q  = (const float*)d_in[0];
    const float* k  = (const float*)d_in[1];
    const float* v  = (const float*)d_in[2];
    const float* sp = (const float*)d_in[3];
    const float* w  = (const float*)d_in[4];
    const float* b  = (const float*)d_in[5];
    float* out = (float*)d_out;

    static bool init = false;
    if (!init){
        init = true;
        cudaFuncSetAttribute(k_attn, cudaFuncAttributeMaxDynamicSharedMemorySize, ATTN_SMEM);
    }

    k_kv<<<NHH*CHUNKS, 64>>>(k, v, sp);
    k_kvreduce<<<512, 128>>>();
    k_attn<<<NHH*(LL/TILE_L), 256, ATTN_SMEM>>>(q, v, w, b, sp, out);
}

// round 8
// speedup vs baseline: 1.0240x; 1.0240x over previous
#include <cuda_runtime.h>
#include <cuda_bf16.h>
#include <math.h>

#define NB 8
#define LL 4096
#define HH 8
#define DD 64
#define HT 64
#define WD 64
#define NHH (NB*HH)          // 64
#define CHUNKS 32
#define CROWS (LL/CHUNKS)    // 128
#define ROWSTRIDE (HH*DD)    // 512
#define TILE_L 128
#define TY 16

typedef unsigned long long ull;

// ---------------- device scratch ----------------
__device__ float g_kvp[CHUNKS][NHH][DD][DD];   // 33.5 MB partials
__device__ float g_ksp[CHUNKS][NHH][DD];
__device__ float g_kv[NHH][DD][DD];
__device__ float g_ksum[NHH][DD];

// ---------------- f32x2 helpers ----------------
__device__ __forceinline__ void ffma2(ull& d, ull a, ull b){
    asm("fma.rn.f32x2 %0, %1, %2, %0;" : "+l"(d) : "l"(a), "l"(b));
}
__device__ __forceinline__ ull pack2(float lo, float hi){
    ull r; asm("mov.b64 %0, {%1, %2};" : "=l"(r) : "f"(lo), "f"(hi)); return r;
}
__device__ __forceinline__ void unpack2(ull v, float& lo, float& hi){
    asm("mov.b64 {%0, %1}, %2;" : "=f"(lo), "=f"(hi) : "l"(v));
}
__device__ __forceinline__ void f4add(float4& a, const float4 b){
    a.x += b.x; a.y += b.y; a.z += b.z; a.w += b.w;
}
__device__ __forceinline__ float softinv(float p){
    float s = (p > 20.f) ? p : log1pf(expf(p));
    return 1.f / s;
}

// ---------------- K1: kv & ksum partials ----------------
// 64 threads/block, one (chunk, nh), stages of 64 rows, XOR-swizzled tiles.
// Transform stores UNSCALED cc then rescales in smem (kills c[16] regs).
// GEMM thread tile: 8 d-rows x 8 j-cols (8x4 f32x2 accumulators).
__global__ void __launch_bounds__(64) k_kv(const float* __restrict__ keys,
                                           const float* __restrict__ values,
                                           const float* __restrict__ sp){
    __shared__ float4 kt4[64*16];
    __shared__ float4 vt4[64*16];
    __shared__ float invs[64];

    const int nh    = blockIdx.x & (NHH-1);
    const int chunk = blockIdx.x >> 6;
    const int n = nh >> 3, h = nh & 7;
    const int t = threadIdx.x;
    const int td = t >> 3, tj = t & 7;
    invs[t] = softinv(sp[t]);
    __syncthreads();

    const size_t base = ((size_t)(n*LL + chunk*CROWS)*HH + h)*DD;

    ull acc[8][4];
    #pragma unroll
    for (int a = 0; a < 8; ++a)
        #pragma unroll
        for (int b = 0; b < 4; ++b) acc[a][b] = 0ull;
    float4 ksA = make_float4(0,0,0,0), ksB = make_float4(0,0,0,0);

    for (int stage = 0; stage < CROWS/64; ++stage){
        __syncthreads();
        // transform row r: stage unscaled cc + v, then rescale own row in smem
        const int r = stage*64 + t;
        const float4* kp = (const float4*)(keys   + base + (size_t)r*ROWSTRIDE);
        const float4* vp = (const float4*)(values + base + (size_t)r*ROWSTRIDE);
        const int swb = t & 15;
        float s2 = 0.f, s6 = 0.f;
        #pragma unroll
        for (int i = 0; i < 16; ++i){
            float4 k4 = kp[i], iv = ((const float4*)invs)[i], x, cc;
            x.x = (fmaxf(k4.x,0.f)+1e-6f)*iv.x;
            x.y = (fmaxf(k4.y,0.f)+1e-6f)*iv.y;
            x.z = (fmaxf(k4.z,0.f)+1e-6f)*iv.z;
            x.w = (fmaxf(k4.w,0.f)+1e-6f)*iv.w;
            cc.x = x.x*x.x*x.x; cc.y = x.y*x.y*x.y;
            cc.z = x.z*x.z*x.z; cc.w = x.w*x.w*x.w;
            s2 += x.x*x.x + x.y*x.y + x.z*x.z + x.w*x.w;
            s6 += cc.x*cc.x + cc.y*cc.y + cc.z*cc.z + cc.w*cc.w;
            kt4[t*16 + (i ^ swb)] = cc;
            vt4[t*16 + (i ^ swb)] = vp[i];
        }
        const float rt = sqrtf(s2/s6);
        #pragma unroll
        for (int i = 0; i < 16; ++i){
            float4 cc = kt4[t*16 + (i ^ swb)];
            cc.x *= rt; cc.y *= rt; cc.z *= rt; cc.w *= rt;
            kt4[t*16 + (i ^ swb)] = cc;
        }
        __syncthreads();

        #pragma unroll 4
        for (int r2 = 0; r2 < 64; ++r2){
            const int sw = r2 & 15;
            const float4 a0 = kt4[r2*16 + ((td*2  ) ^ sw)];
            const float4 a1 = kt4[r2*16 + ((td*2+1) ^ sw)];
            const ulonglong2 b0 = *(const ulonglong2*)&vt4[r2*16 + ((tj*2  ) ^ sw)];
            const ulonglong2 b1 = *(const ulonglong2*)&vt4[r2*16 + ((tj*2+1) ^ sw)];
            if (tj == 0){ f4add(ksA, a0); f4add(ksB, a1); }
            const float ka[8] = {a0.x,a0.y,a0.z,a0.w,a1.x,a1.y,a1.z,a1.w};
            #pragma unroll
            for (int dd = 0; dd < 8; ++dd){
                const ull k2 = pack2(ka[dd], ka[dd]);
                ffma2(acc[dd][0], k2, b0.x);
                ffma2(acc[dd][1], k2, b0.y);
                ffma2(acc[dd][2], k2, b1.x);
                ffma2(acc[dd][3], k2, b1.y);
            }
        }
    }

    #pragma unroll
    for (int dd = 0; dd < 8; ++dd){
        ull* o = (ull*)&g_kvp[chunk][nh][td*8+dd][tj*8];
        o[0]=acc[dd][0]; o[1]=acc[dd][1]; o[2]=acc[dd][2]; o[3]=acc[dd][3];
    }
    if (tj == 0){
        ((float4*)&g_ksp[chunk][nh][td*8])[0] = ksA;
        ((float4*)&g_ksp[chunk][nh][td*8])[1] = ksB;
    }
}

// ---------------- K1b: parallel deterministic chunk reduction ----------------
__global__ void __launch_bounds__(128) k_kvreduce(){
    const int gid = blockIdx.x*128 + threadIdx.x;   // 65536 float4 outputs
    const float4* src = (const float4*)g_kvp;
    float4 s = make_float4(0,0,0,0);
    #pragma unroll
    for (int c = 0; c < CHUNKS; ++c) f4add(s, src[(size_t)c*65536 + gid]);
    ((float4*)g_kv)[gid] = s;
    if (gid < NHH*DD){
        const float* ks = (const float*)g_ksp;
        float acc = 0.f;
        #pragma unroll
        for (int c = 0; c < CHUNKS; ++c) acc += ks[c*NHH*DD + gid];
        ((float*)g_ksum)[gid] = acc;
    }
}

// ---------------- K2: attention GEMM (R5-proven, RMW onto conv output) ----------------
#define ATTN_SMEM ((64*68 + 64*132 + 64 + 64 + 128)*4)
__global__ void __launch_bounds__(256) k_attn(const float* __restrict__ qin,
                                              const float* __restrict__ sp,
                                              float* __restrict__ out){
    extern __shared__ float sm[];
    float* kv_s   = sm;                  // 64 x 68
    float* qt     = sm + 64*68;          // 64 x 132
    float* ksum_s = sm + 64*68 + 64*132; // 64
    float* invs   = ksum_s + 64;         // 64
    float* m_s    = invs + 64;           // 128

    const int lt = blockIdx.x & 31;
    const int nh = blockIdx.x >> 5;
    const int n = nh >> 3, h = nh & 7;
    const int t = threadIdx.x;

    {   // load kv into padded smem
        const int d = t >> 2, qf = t & 3;
        const float4* src = (const float4*)&g_kv[nh][d][0];
        float4* dst = (float4*)&kv_s[d*68];
        #pragma unroll
        for (int i = 0; i < 4; ++i) dst[qf*4 + i] = src[qf*4 + i];
        if (t < DD){ ksum_s[t] = g_ksum[nh][t]; invs[t] = softinv(sp[t]); }
    }
    __syncthreads();

    const size_t base = ((size_t)(n*LL + lt*TILE_L)*HH + h)*DD;

    if (t < TILE_L){   // transform row t: store UNSCALED cc, save m for epilogue
        const float4* qp = (const float4*)(qin + base + (size_t)t*ROWSTRIDE);
        float s2 = 0.f, s6 = 0.f, sd = 0.f;
        #pragma unroll
        for (int i = 0; i < 16; ++i){
            float4 q4 = qp[i];
            float4 iv = ((const float4*)invs)[i];
            float4 ks = ((const float4*)ksum_s)[i];
            float4 x, cc;
            x.x = (fmaxf(q4.x,0.f)+1e-6f)*iv.x;
            x.y = (fmaxf(q4.y,0.f)+1e-6f)*iv.y;
            x.z = (fmaxf(q4.z,0.f)+1e-6f)*iv.z;
            x.w = (fmaxf(q4.w,0.f)+1e-6f)*iv.w;
            cc.x = x.x*x.x*x.x; cc.y = x.y*x.y*x.y;
            cc.z = x.z*x.z*x.z; cc.w = x.w*x.w*x.w;
            s2 += x.x*x.x + x.y*x.y + x.z*x.z + x.w*x.w;
            s6 += cc.x*cc.x + cc.y*cc.y + cc.z*cc.z + cc.w*cc.w;
            sd += cc.x*ks.x + cc.y*ks.y + cc.z*ks.z + cc.w*ks.w;
            qt[(4*i+0)*132 + t] = cc.x;
            qt[(4*i+1)*132 + t] = cc.y;
            qt[(4*i+2)*132 + t] = cc.z;
            qt[(4*i+3)*132 + t] = cc.w;
        }
        const float rt = sqrtf(s2/s6);
        const float z  = 1.f / (rt*sd + 1e-6f);
        m_s[t] = rt * z;
    }
    __syncthreads();

    const int tr = t >> 4, tc = t & 15;
    ull acc[4][4];
    #pragma unroll
    for (int a = 0; a < 4; ++a)
        #pragma unroll
        for (int b = 0; b < 4; ++b) acc[a][b] = 0ull;

    #pragma unroll 8
    for (int d = 0; d < DD; ++d){
        const ulonglong2 A0 = *(const ulonglong2*)&qt[d*132 + tr*8];
        const ulonglong2 A1 = *(const ulonglong2*)&qt[d*132 + tr*8 + 4];
        const float4 b4 = *(const float4*)&kv_s[d*68 + tc*4];
        const ull b0 = pack2(b4.x,b4.x), b1 = pack2(b4.y,b4.y);
        const ull b2 = pack2(b4.z,b4.z), b3 = pack2(b4.w,b4.w);
        ffma2(acc[0][0], A0.x, b0); ffma2(acc[0][1], A0.x, b1);
        ffma2(acc[0][2], A0.x, b2); ffma2(acc[0][3], A0.x, b3);
        ffma2(acc[1][0], A0.y, b0); ffma2(acc[1][1], A0.y, b1);
        ffma2(acc[1][2], A0.y, b2); ffma2(acc[1][3], A0.y, b3);
        ffma2(acc[2][0], A1.x, b0); ffma2(acc[2][1], A1.x, b1);
        ffma2(acc[2][2], A1.x, b2); ffma2(acc[2][3], A1.x, b3);
        ffma2(acc[3][0], A1.y, b0); ffma2(acc[3][1], A1.y, b1);
        ffma2(acc[3][2], A1.y, b2); ffma2(acc[3][3], A1.y, b3);
    }

    // Epilogue: out += m[row] * acc  (out holds conv(v)+bias)
    float* ob = out + base + (size_t)(tr*8)*ROWSTRIDE + tc*4;
    #pragma unroll
    for (int rp = 0; rp < 4; ++rp){
        const float mlo = m_s[tr*8 + 2*rp];
        const float mhi = m_s[tr*8 + 2*rp + 1];
        float lo[4], hi[4];
        #pragma unroll
        for (int c = 0; c < 4; ++c) unpack2(acc[rp][c], lo[c], hi[c]);
        float4* pe = (float4*)(ob + (size_t)(2*rp  )*ROWSTRIDE);
        float4* po = (float4*)(ob + (size_t)(2*rp+1)*ROWSTRIDE);
        float4 e = pe[0], o = po[0];
        pe[0] = make_float4(fmaf(mlo,lo[0],e.x), fmaf(mlo,lo[1],e.y),
                            fmaf(mlo,lo[2],e.z), fmaf(mlo,lo[3],e.w));
        po[0] = make_float4(fmaf(mhi,hi[0],o.x), fmaf(mhi,hi[1],o.y),
                            fmaf(mhi,hi[2],o.z), fmaf(mhi,hi[3],o.w));
    }
}

// ---------------- K3: depthwise 5x5 conv (R2/R5-proven), out = conv(v)+bias ----------------
#define K3_SMEM_FLOATS (5*68*64 + 25*64)
__global__ void __launch_bounds__(256,2) k_conv(const float* __restrict__ vin,
                                                const float* __restrict__ wt,
                                                const float* __restrict__ bias,
                                                float* __restrict__ out){
    extern __shared__ float sm[];
    float* ring = sm;                 // 5*68*64
    float* wsh  = sm + 5*68*64;       // 25*64

    const int yt = blockIdx.x & 3;
    const int nh = blockIdx.x >> 2;
    const int n = nh >> 3, h = nh & 7;
    const int t = threadIdx.x;
    const int dp = t & 31;
    const int xg = t >> 5;

    for (int i = t; i < 25*DD; i += 256){
        int tap = i >> 6, d = i & 63;
        wsh[i] = wt[d*25 + tap];
    }
    {
        int xi = t >> 6;
        int d  = t & 63;
        int xp = (xi < 2) ? xi : (64 + xi);
        #pragma unroll
        for (int s = 0; s < 5; ++s) ring[(s*68 + xp)*64 + d] = 0.f;
    }
    __syncthreads();

    ull wr[25];
    #pragma unroll
    for (int i = 0; i < 25; ++i) wr[i] = *(const ull*)&wsh[i*64 + 2*dp];
    const ull bias2 = *(const ull*)(bias + 2*dp);

    const int y0 = yt*TY;

    auto loadrow = [&](int y){
        const int s = (y + 10) % 5;
        float* dst = ring + (size_t)s*68*64;
        if (y < 0 || y >= HT){
            #pragma unroll
            for (int k2 = 0; k2 < 4; ++k2){
                int f = t + k2*256;
                int x = f >> 4, dq = f & 15;
                *(float4*)&dst[(x+2)*64 + dq*4] = make_float4(0.f,0.f,0.f,0.f);
            }
        } else {
            const float* src = vin + ((size_t)(n*LL + y*WD)*HH + h)*DD;
            #pragma unroll
            for (int k2 = 0; k2 < 4; ++k2){
                int f = t + k2*256;
                int x = f >> 4, dq = f & 15;
                *(float4*)&dst[(x+2)*64 + dq*4] =
                    *(const float4*)&src[(size_t)x*ROWSTRIDE + dq*4];
            }
        }
    };

    loadrow(y0-2); loadrow(y0-1); loadrow(y0); loadrow(y0+1);

    for (int yo = 0; yo < TY; ++yo){
        const int y = y0 + yo;
        loadrow(y+2);
        __syncthreads();

        ull acc[8];
        #pragma unroll
        for (int xx = 0; xx < 8; ++xx) acc[xx] = bias2;
        const int x0 = xg*8;

        #pragma unroll
        for (int dy = 0; dy < 5; ++dy){
            const int s = (y + dy + 8) % 5;
            const float* rp = ring + (size_t)s*68*64 + 2*dp;
            ull win[12];
            #pragma unroll
            for (int i = 0; i < 12; ++i) win[i] = *(const ull*)&rp[(x0+i)*64];
            #pragma unroll
            for (int xx = 0; xx < 8; ++xx)
                #pragma unroll
                for (int dx = 0; dx < 5; ++dx)
                    ffma2(acc[xx], wr[dy*5+dx], win[xx+dx]);
        }

        float* ob = out + ((size_t)(n*LL + y*WD + x0)*HH + h)*DD + 2*dp;
        #pragma unroll
        for (int xx = 0; xx < 8; ++xx)
            *(ull*)(ob + (size_t)xx*ROWSTRIDE) = acc[xx];
        __syncthreads();
    }
}

// ---------------- launch (fork-join: conv overlaps kv+reduce) ----------------
extern "C" void kernel_launch(void* const* d_in, const int* in_sizes, int n_in,
                              void* d_out, int out_size){
    const float* q  = (const float*)d_in[0];
    const float* k  = (const float*)d_in[1];
    const float* v  = (const float*)d_in[2];
    const float* sp = (const float*)d_in[3];
    const float* w  = (const float*)d_in[4];
    const float* b  = (const float*)d_in[5];
    float* out = (float*)d_out;

    static cudaStream_t s2 = nullptr;
    static cudaEvent_t evFork = nullptr, evJoin = nullptr;
    if (!s2){
        cudaStreamCreateWithFlags(&s2, cudaStreamNonBlocking);
        cudaEventCreateWithFlags(&evFork, cudaEventDisableTiming);
        cudaEventCreateWithFlags(&evJoin, cudaEventDisableTiming);
        cudaFuncSetAttribute(k_attn, cudaFuncAttributeMaxDynamicSharedMemorySize, ATTN_SMEM);
        cudaFuncSetAttribute(k_conv, cudaFuncAttributeMaxDynamicSharedMemorySize, K3_SMEM_FLOATS*4);
    }

    // fork: conv (writes out = conv+bias) runs concurrently with kv pipeline
    cudaEventRecord(evFork, 0);
    cudaStreamWaitEvent(s2, evFork, 0);
    k_conv<<<NHH*(HT/TY), 256, K3_SMEM_FLOATS*4, s2>>>(v, w, b, out);
    cudaEventRecord(evJoin, s2);

    k_kv<<<NHH*CHUNKS, 64>>>(k, v, sp);
    k_kvreduce<<<512, 128>>>();

    // join: attn RMW-adds attention onto conv output
    cudaStreamWaitEvent(0, evJoin, 0);
    k_attn<<<NHH*(LL/TILE_L), 256, ATTN_SMEM>>>(q, sp, out);
}